// round 6
// baseline (speedup 1.0000x reference)
#include <cuda_runtime.h>
#include <cuda_bf16.h>
#include <cstdint>

#define NQ 50001
#define TI 128
#define NBLK 391

// feat smem row: [hi bf16 k0..191 | lo bf16 k0..191 | pad16] = 784 B
#define ROWB 784
#define SM_FEAT 0
#define SM_L    (SM_FEAT + 128 * ROWB)        // logits [128 i][65 f]
#define SM_PART (SM_L + 128 * 65 * 4)         // partials [8][128] f
#define SM_TOTAL (SM_PART + 8 * 128 * 4)      // 137,728 B

__device__ float g_M1f[512 * 50];
__device__ uint4 g_WA[384 * 2 * 32];          // [(s*4+c)*12+t][term][lane] A-frags (W)
__device__ uint4 g_KA[32 * 2 * 32];           // [c*8+t][term][lane] A-frags (Kmem)
__device__ float g_pred[NQ];

__device__ __forceinline__ uint16_t bhi(float x) {
    return __bfloat16_as_ushort(__float2bfloat16(x));
}
__device__ __forceinline__ uint16_t blo(float x) {
    float h = __bfloat162float(__float2bfloat16(x));
    return __bfloat16_as_ushort(__float2bfloat16(x - h));
}
__device__ __forceinline__ uint32_t pk2(uint16_t a, uint16_t b) {
    return (uint32_t)a | ((uint32_t)b << 16);
}
__device__ __forceinline__ uint32_t s2u(const void* p) {
    uint32_t a;
    asm("{ .reg .u64 t; cvta.to.shared.u64 t, %1; cvt.u32.u64 %0, t; }" : "=r"(a) : "l"(p));
    return a;
}
__device__ __forceinline__ void ldm4(uint32_t addr, uint32_t* r) {
    asm volatile("ldmatrix.sync.aligned.m8n8.x4.shared.b16 {%0,%1,%2,%3}, [%4];"
                 : "=r"(r[0]), "=r"(r[1]), "=r"(r[2]), "=r"(r[3]) : "r"(addr));
}
__device__ __forceinline__ void mma16816(float* c, const uint32_t* a, uint32_t b0, uint32_t b1) {
    asm volatile("mma.sync.aligned.m16n8k16.row.col.f32.bf16.bf16.f32 "
                 "{%0,%1,%2,%3}, {%4,%5,%6,%7}, {%8,%9}, {%0,%1,%2,%3};"
                 : "+f"(c[0]), "+f"(c[1]), "+f"(c[2]), "+f"(c[3])
                 : "r"(a[0]), "r"(a[1]), "r"(a[2]), "r"(a[3]), "r"(b0), "r"(b1));
}
// per-lane ldmatrix address for B tile-pair (i0..i0+15) x (k-step bytes kb0..+31)
__device__ __forceinline__ uint32_t baddr(uint32_t fb, int lane, int i0, int kb0) {
    int row = i0 + (lane & 7) + ((lane & 16) ? 8 : 0);
    int col = (lane & 8) ? 16 : 0;
    return fb + row * ROWB + kb0 + col;
}

// ---------------------------------------------------------------- prep1: M1
__global__ void k_prep1(const float* __restrict__ Wf, const float* __restrict__ V) {
    __shared__ float wrow[256];
    __shared__ float p2[100];
    const int b = blockIdx.x, t = threadIdx.x;   // 512 x 128
    for (int e = t; e < 256; e += 128) wrow[e] = Wf[b * 384 + e];
    __syncthreads();
    if (t < 100) {
        int m = t >> 1, half = (t & 1) * 128;
        const float* vp = V + m * 256 + half;
        const float* wp2 = wrow + half;
        float s = 0.f;
#pragma unroll 16
        for (int v = 0; v < 128; v++) s += wp2[v] * __ldg(vp + v);
        p2[t] = s;
    }
    __syncthreads();
    if (t < 50) g_M1f[b * 50 + t] = p2[2 * t] + p2[2 * t + 1];
}

// ---------------------------------------------------------------- prep2: frag pack
__global__ void k_prep2(const float* __restrict__ Wf, const float* __restrict__ Km) {
    const int b = blockIdx.x, lane = threadIdx.x;   // 416 x 32
    const int q = lane >> 2, r = lane & 3;
    if (b < 384) {
        const int s = b / 48, rem = b % 48, c = rem / 12, t = rem % 12;
        const int h0 = s * 64 + c * 16 + q, h1 = h0 + 8;
        const int k0 = t * 16 + 2 * r;
        float v[8];
#pragma unroll
        for (int j = 0; j < 8; j++) {
            int h = (j & 1) ? h1 : h0;
            int k = k0 + ((j >> 2) ? 8 : 0) + ((j >> 1) & 1);
            v[j] = (k < 128) ? Wf[h * 384 + 256 + k]
                             : ((k < 178) ? g_M1f[h * 50 + (k - 128)] : 0.f);
        }
        uint4 hi, lo;
        hi.x = pk2(bhi(v[0]), bhi(v[2]));  lo.x = pk2(blo(v[0]), blo(v[2]));
        hi.y = pk2(bhi(v[1]), bhi(v[3]));  lo.y = pk2(blo(v[1]), blo(v[3]));
        hi.z = pk2(bhi(v[4]), bhi(v[6]));  lo.z = pk2(blo(v[4]), blo(v[6]));
        hi.w = pk2(bhi(v[5]), bhi(v[7]));  lo.w = pk2(blo(v[5]), blo(v[7]));
        const int fs = (s * 4 + c) * 12 + t;
        g_WA[(fs * 2 + 0) * 32 + lane] = hi;
        g_WA[(fs * 2 + 1) * 32 + lane] = lo;
    } else {
        const int kb = b - 384, c = kb / 8, t = kb % 8;
        const int m0 = c * 16 + q, m1 = m0 + 8;
        const int k0 = t * 16 + 2 * r;
        float v[8];
#pragma unroll
        for (int j = 0; j < 8; j++) {
            int m = (j & 1) ? m1 : m0;
            int k = k0 + ((j >> 2) ? 8 : 0) + ((j >> 1) & 1);
            v[j] = (m < 50) ? Km[m * 128 + k] : 0.f;
        }
        uint4 hi, lo;
        hi.x = pk2(bhi(v[0]), bhi(v[2]));  lo.x = pk2(blo(v[0]), blo(v[2]));
        hi.y = pk2(bhi(v[1]), bhi(v[3]));  lo.y = pk2(blo(v[1]), blo(v[3]));
        hi.z = pk2(bhi(v[4]), bhi(v[6]));  lo.z = pk2(blo(v[4]), blo(v[6]));
        hi.w = pk2(bhi(v[5]), bhi(v[7]));  lo.w = pk2(blo(v[5]), blo(v[7]));
        const int fs = c * 8 + t;
        g_KA[(fs * 2 + 0) * 32 + lane] = hi;
        g_KA[(fs * 2 + 1) * 32 + lane] = lo;
    }
}

// ---------------------------------------------------------------- main
__global__ void __launch_bounds__(256) k_main(
    const float* __restrict__ embed, const float* __restrict__ bf,
    const float* __restrict__ Wp,    const float* __restrict__ bp)
{
    extern __shared__ __align__(16) unsigned char sm[];
    const int tid = threadIdx.x, wid = tid >> 5, lane = tid & 31;
    const int q = lane >> 2, r = lane & 3;
    const int base = blockIdx.x * TI;
    const uint32_t fb = s2u(sm) + SM_FEAT;
    float* L    = (float*)(sm + SM_L);
    float* part = (float*)(sm + SM_PART);

    // ---- stage embed -> feat rows (hi/lo bf16) ----
    for (int id = tid; id < 4096; id += 256) {
        int row = id >> 5, kq = id & 31;
        int rr = base + row; if (rr >= NQ) rr = NQ - 1;
        float4 v = __ldg((const float4*)&embed[rr * 128 + kq * 4]);
        uint2 h = make_uint2(pk2(bhi(v.x), bhi(v.y)), pk2(bhi(v.z), bhi(v.w)));
        uint2 l = make_uint2(pk2(blo(v.x), blo(v.y)), pk2(blo(v.z), blo(v.w)));
        *(uint2*)(sm + SM_FEAT + row * ROWB + kq * 8)       = h;
        *(uint2*)(sm + SM_FEAT + row * ROWB + 384 + kq * 8) = l;
    }
    if (tid < 128) {    // zero k = 128..191 (hi bytes 256..384, lo 640..768)
        uint4 z = make_uint4(0, 0, 0, 0);
#pragma unroll
        for (int j = 0; j < 8; j++) {
            *(uint4*)(sm + SM_FEAT + tid * ROWB + 256 + j * 16) = z;
            *(uint4*)(sm + SM_FEAT + tid * ROWB + 640 + j * 16) = z;
        }
    }
    __syncthreads();

    // ---- GEMM1: logits[m 64][i 128] = Kmem . feat^T ----
    {
        const int c = wid & 3, half = wid >> 2, ib = half * 64;
        float cf[8][4];
#pragma unroll
        for (int n = 0; n < 8; n++)
#pragma unroll
            for (int j = 0; j < 4; j++) cf[n][j] = 0.f;
#pragma unroll 1
        for (int t = 0; t < 8; t++) {
            uint4 fah = __ldg(&g_KA[((c * 8 + t) * 2 + 0) * 32 + lane]);
            uint4 fal = __ldg(&g_KA[((c * 8 + t) * 2 + 1) * 32 + lane]);
            uint32_t ah[4] = {fah.x, fah.y, fah.z, fah.w};
            uint32_t al[4] = {fal.x, fal.y, fal.z, fal.w};
#pragma unroll
            for (int n2 = 0; n2 < 4; n2++) {
                uint32_t bh[4], bl[4];
                ldm4(baddr(fb, lane, ib + n2 * 16, t * 32), bh);
                ldm4(baddr(fb, lane, ib + n2 * 16, 384 + t * 32), bl);
                mma16816(cf[n2 * 2],     ah, bh[0], bh[1]);
                mma16816(cf[n2 * 2],     al, bh[0], bh[1]);
                mma16816(cf[n2 * 2],     ah, bl[0], bl[1]);
                mma16816(cf[n2 * 2 + 1], ah, bh[2], bh[3]);
                mma16816(cf[n2 * 2 + 1], al, bh[2], bh[3]);
                mma16816(cf[n2 * 2 + 1], ah, bl[2], bl[3]);
            }
        }
        const int m0 = c * 16 + q;
#pragma unroll
        for (int n = 0; n < 8; n++) {
            int i = ib + n * 8 + 2 * r;
            L[i * 65 + m0]           = cf[n][0];
            L[(i + 1) * 65 + m0]     = cf[n][1];
            L[i * 65 + m0 + 8]       = cf[n][2];
            L[(i + 1) * 65 + m0 + 8] = cf[n][3];
        }
    }
    __syncthreads();

    // ---- softmax per i (thread = one i), write probs into feat k=128..177 ----
    if (tid < 128) {
        const float* row = &L[tid * 65];
        float lg[50], mx = -1e30f;
#pragma unroll
        for (int m = 0; m < 50; m++) { lg[m] = row[m]; mx = fmaxf(mx, lg[m]); }
        float s = 0.f;
#pragma unroll
        for (int m = 0; m < 50; m++) { lg[m] = __expf(lg[m] - mx); s += lg[m]; }
        float inv = 1.f / s;
#pragma unroll
        for (int j = 0; j < 25; j++) {
            float p0 = lg[2 * j] * inv, p1 = lg[2 * j + 1] * inv;
            *(uint32_t*)(sm + SM_FEAT + tid * ROWB + 256 + 4 * j) = pk2(bhi(p0), bhi(p1));
            *(uint32_t*)(sm + SM_FEAT + tid * ROWB + 640 + 4 * j) = pk2(blo(p0), blo(p1));
        }
    }
    __syncthreads();

    // ---- GEMM2: per warp strip s (64 h), 2 chunk-pairs; A-stationary over 2 chunks ----
    {
        const int s = wid;
#pragma unroll 1
        for (int pair = 0; pair < 2; pair++) {
            const int c0 = pair * 2;
            float cf[2][16][4];
#pragma unroll
            for (int u = 0; u < 2; u++)
#pragma unroll
                for (int n = 0; n < 16; n++)
#pragma unroll
                    for (int j = 0; j < 4; j++) cf[u][n][j] = 0.f;
#pragma unroll 1
            for (int t = 0; t < 12; t++) {
                const int fs0 = (s * 4 + c0) * 12 + t;
                const int fs1 = (s * 4 + c0 + 1) * 12 + t;
                uint4 f0h = __ldg(&g_WA[(fs0 * 2 + 0) * 32 + lane]);
                uint4 f0l = __ldg(&g_WA[(fs0 * 2 + 1) * 32 + lane]);
                uint4 f1h = __ldg(&g_WA[(fs1 * 2 + 0) * 32 + lane]);
                uint4 f1l = __ldg(&g_WA[(fs1 * 2 + 1) * 32 + lane]);
                uint32_t a0h[4] = {f0h.x, f0h.y, f0h.z, f0h.w};
                uint32_t a0l[4] = {f0l.x, f0l.y, f0l.z, f0l.w};
                uint32_t a1h[4] = {f1h.x, f1h.y, f1h.z, f1h.w};
                uint32_t a1l[4] = {f1l.x, f1l.y, f1l.z, f1l.w};
#pragma unroll
                for (int n2 = 0; n2 < 8; n2++) {
                    uint32_t bh[4], bl[4];
                    ldm4(baddr(fb, lane, n2 * 16, t * 32), bh);
                    ldm4(baddr(fb, lane, n2 * 16, 384 + t * 32), bl);
                    mma16816(cf[0][n2 * 2],     a0h, bh[0], bh[1]);
                    mma16816(cf[0][n2 * 2],     a0l, bh[0], bh[1]);
                    mma16816(cf[0][n2 * 2],     a0h, bl[0], bl[1]);
                    mma16816(cf[0][n2 * 2 + 1], a0h, bh[2], bh[3]);
                    mma16816(cf[0][n2 * 2 + 1], a0l, bh[2], bh[3]);
                    mma16816(cf[0][n2 * 2 + 1], a0h, bl[2], bl[3]);
                    mma16816(cf[1][n2 * 2],     a1h, bh[0], bh[1]);
                    mma16816(cf[1][n2 * 2],     a1l, bh[0], bh[1]);
                    mma16816(cf[1][n2 * 2],     a1h, bl[0], bl[1]);
                    mma16816(cf[1][n2 * 2 + 1], a1h, bh[2], bh[3]);
                    mma16816(cf[1][n2 * 2 + 1], a1l, bh[2], bh[3]);
                    mma16816(cf[1][n2 * 2 + 1], a1h, bl[2], bl[3]);
                }
            }
            // epilogue: relu/wp for both chunks -> transient pacc -> reduce -> part
            float pacc[32];
#pragma unroll
            for (int j = 0; j < 32; j++) pacc[j] = 0.f;
#pragma unroll
            for (int u = 0; u < 2; u++) {
                const int h0 = s * 64 + (c0 + u) * 16 + q, h1 = h0 + 8;
                float b0 = __ldg(&bf[h0]), b1 = __ldg(&bf[h1]);
                float w0 = __ldg(&Wp[h0]), w1 = __ldg(&Wp[h1]);
#pragma unroll
                for (int n = 0; n < 16; n++) {
                    pacc[2 * n]     += fmaxf(cf[u][n][0] + b0, 0.f) * w0
                                     + fmaxf(cf[u][n][2] + b1, 0.f) * w1;
                    pacc[2 * n + 1] += fmaxf(cf[u][n][1] + b0, 0.f) * w0
                                     + fmaxf(cf[u][n][3] + b1, 0.f) * w1;
                }
            }
#pragma unroll
            for (int j = 0; j < 32; j++) {
                pacc[j] += __shfl_xor_sync(0xffffffffu, pacc[j], 4);
                pacc[j] += __shfl_xor_sync(0xffffffffu, pacc[j], 8);
                pacc[j] += __shfl_xor_sync(0xffffffffu, pacc[j], 16);
            }
            if (lane < 4) {
#pragma unroll
                for (int n = 0; n < 16; n++) {
                    int i = n * 8 + 2 * lane;
                    if (pair == 0) {
                        part[s * 128 + i]     = pacc[2 * n];
                        part[s * 128 + i + 1] = pacc[2 * n + 1];
                    } else {
                        part[s * 128 + i]     += pacc[2 * n];
                        part[s * 128 + i + 1] += pacc[2 * n + 1];
                    }
                }
            }
        }
    }
    __syncthreads();

    // ---- final reduce + sigmoid ----
    if (tid < 128) {
        float sum = __ldg(bp);
#pragma unroll
        for (int s = 0; s < 8; s++) sum += part[s * 128 + tid];
        int rr = base + tid;
        if (rr < NQ) g_pred[rr] = 1.f / (1.f + __expf(-sum));
    }
}

// ---------------------------------------------------------------- gather
__global__ void k_gather(const int* __restrict__ q, float* __restrict__ out, int n) {
    int j = (blockIdx.x * blockDim.x + threadIdx.x) * 4;
    if (j + 3 < n) {
        int4 qv = *(const int4*)(q + j);
        float4 o;
        o.x = g_pred[(unsigned)qv.x < NQ ? qv.x : NQ - 1];
        o.y = g_pred[(unsigned)qv.y < NQ ? qv.y : NQ - 1];
        o.z = g_pred[(unsigned)qv.z < NQ ? qv.z : NQ - 1];
        o.w = g_pred[(unsigned)qv.w < NQ ? qv.w : NQ - 1];
        *(float4*)(out + j) = o;
    } else {
        for (; j < n; j++) {
            int idx = q[j];
            out[j] = g_pred[(unsigned)idx < NQ ? idx : NQ - 1];
        }
    }
}

// ---------------------------------------------------------------- launcher
extern "C" void kernel_launch(void* const* d_in, const int* in_sizes, int n_in,
                              void* d_out, int out_size) {
    const int*   q     = (const int*)  d_in[0];
    const float* Kmem  = (const float*)d_in[2];
    const float* V     = (const float*)d_in[3];
    const float* embed = (const float*)d_in[4];
    const float* Wf    = (const float*)d_in[9];
    const float* bf    = (const float*)d_in[10];
    const float* Wp    = (const float*)d_in[11];
    const float* bp    = (const float*)d_in[12];

    k_prep1<<<512, 128>>>(Wf, V);
    k_prep2<<<416, 32>>>(Wf, Kmem);

    cudaFuncSetAttribute(k_main, cudaFuncAttributeMaxDynamicSharedMemorySize, SM_TOTAL);
    k_main<<<NBLK, 256, SM_TOTAL>>>(embed, bf, Wp, bp);

    k_gather<<<(out_size + 1023) / 1024, 256>>>(q, (float*)d_out, out_size);
}

// round 7
// speedup vs baseline: 1.0569x; 1.0569x over previous
#include <cuda_runtime.h>
#include <cuda_bf16.h>
#include <cstdint>

#define NQ 50001
#define TI 128
#define NBLK 391

// feat smem row: [hi bf16 k0..191 | lo bf16 k0..191 | pad16] = 784 B
#define ROWB 784
#define SM_FEAT 0
#define SM_L    (SM_FEAT + 128 * ROWB)        // logits [128 i][65 f]
#define SM_PART (SM_L + 128 * 65 * 4)         // partials [16][64] f
#define SM_TOTAL (SM_PART + 16 * 64 * 4)      // 137,728 B

__device__ float g_M1f[512 * 50];
__device__ uint4 g_WA[384 * 2 * 32];          // [chunk*12+t][term][lane] A-frags (W)
__device__ uint4 g_KA[32 * 2 * 32];           // [c*8+t][term][lane] A-frags (Kmem)
__device__ float g_pred[NQ];

__device__ __forceinline__ uint16_t bhi(float x) {
    return __bfloat16_as_ushort(__float2bfloat16(x));
}
__device__ __forceinline__ uint16_t blo(float x) {
    float h = __bfloat162float(__float2bfloat16(x));
    return __bfloat16_as_ushort(__float2bfloat16(x - h));
}
__device__ __forceinline__ uint32_t pk2(uint16_t a, uint16_t b) {
    return (uint32_t)a | ((uint32_t)b << 16);
}
__device__ __forceinline__ uint32_t s2u(const void* p) {
    uint32_t a;
    asm("{ .reg .u64 t; cvta.to.shared.u64 t, %1; cvt.u32.u64 %0, t; }" : "=r"(a) : "l"(p));
    return a;
}
__device__ __forceinline__ void ldm4(uint32_t addr, uint32_t* r) {
    asm volatile("ldmatrix.sync.aligned.m8n8.x4.shared.b16 {%0,%1,%2,%3}, [%4];"
                 : "=r"(r[0]), "=r"(r[1]), "=r"(r[2]), "=r"(r[3]) : "r"(addr));
}
__device__ __forceinline__ void mma16816(float* c, const uint32_t* a, uint32_t b0, uint32_t b1) {
    asm volatile("mma.sync.aligned.m16n8k16.row.col.f32.bf16.bf16.f32 "
                 "{%0,%1,%2,%3}, {%4,%5,%6,%7}, {%8,%9}, {%0,%1,%2,%3};"
                 : "+f"(c[0]), "+f"(c[1]), "+f"(c[2]), "+f"(c[3])
                 : "r"(a[0]), "r"(a[1]), "r"(a[2]), "r"(a[3]), "r"(b0), "r"(b1));
}
// per-lane ldmatrix address for B tile-pair (i0..i0+15) x (k-step bytes kb0..+31)
__device__ __forceinline__ uint32_t baddr(uint32_t fb, int lane, int i0, int kb0) {
    int row = i0 + (lane & 7) + ((lane & 16) ? 8 : 0);
    int col = (lane & 8) ? 16 : 0;
    return fb + row * ROWB + kb0 + col;
}

// ---------------------------------------------------------------- prep1: M1
__global__ void k_prep1(const float* __restrict__ Wf, const float* __restrict__ V) {
    __shared__ float wrow[256];
    __shared__ float p2[100];
    const int b = blockIdx.x, t = threadIdx.x;   // 512 x 128
    for (int e = t; e < 256; e += 128) wrow[e] = Wf[b * 384 + e];
    __syncthreads();
    if (t < 100) {
        int m = t >> 1, half = (t & 1) * 128;
        const float* vp = V + m * 256 + half;
        const float* wp2 = wrow + half;
        float s = 0.f;
#pragma unroll 16
        for (int v = 0; v < 128; v++) s += wp2[v] * __ldg(vp + v);
        p2[t] = s;
    }
    __syncthreads();
    if (t < 50) g_M1f[b * 50 + t] = p2[2 * t] + p2[2 * t + 1];
}

// ---------------------------------------------------------------- prep2: frag pack
__global__ void k_prep2(const float* __restrict__ Wf, const float* __restrict__ Km) {
    const int b = blockIdx.x, lane = threadIdx.x;   // 416 x 32
    const int q = lane >> 2, r = lane & 3;
    if (b < 384) {
        const int s = b / 48, rem = b % 48, c = rem / 12, t = rem % 12;
        const int h0 = s * 64 + c * 16 + q, h1 = h0 + 8;
        const int k0 = t * 16 + 2 * r;
        float v[8];
#pragma unroll
        for (int j = 0; j < 8; j++) {
            int h = (j & 1) ? h1 : h0;
            int k = k0 + ((j >> 2) ? 8 : 0) + ((j >> 1) & 1);
            v[j] = (k < 128) ? Wf[h * 384 + 256 + k]
                             : ((k < 178) ? g_M1f[h * 50 + (k - 128)] : 0.f);
        }
        uint4 hi, lo;
        hi.x = pk2(bhi(v[0]), bhi(v[2]));  lo.x = pk2(blo(v[0]), blo(v[2]));
        hi.y = pk2(bhi(v[1]), bhi(v[3]));  lo.y = pk2(blo(v[1]), blo(v[3]));
        hi.z = pk2(bhi(v[4]), bhi(v[6]));  lo.z = pk2(blo(v[4]), blo(v[6]));
        hi.w = pk2(bhi(v[5]), bhi(v[7]));  lo.w = pk2(blo(v[5]), blo(v[7]));
        const int fs = (s * 4 + c) * 12 + t;
        g_WA[(fs * 2 + 0) * 32 + lane] = hi;
        g_WA[(fs * 2 + 1) * 32 + lane] = lo;
    } else {
        const int kb = b - 384, c = kb / 8, t = kb % 8;
        const int m0 = c * 16 + q, m1 = m0 + 8;
        const int k0 = t * 16 + 2 * r;
        float v[8];
#pragma unroll
        for (int j = 0; j < 8; j++) {
            int m = (j & 1) ? m1 : m0;
            int k = k0 + ((j >> 2) ? 8 : 0) + ((j >> 1) & 1);
            v[j] = (m < 50) ? Km[m * 128 + k] : 0.f;
        }
        uint4 hi, lo;
        hi.x = pk2(bhi(v[0]), bhi(v[2]));  lo.x = pk2(blo(v[0]), blo(v[2]));
        hi.y = pk2(bhi(v[1]), bhi(v[3]));  lo.y = pk2(blo(v[1]), blo(v[3]));
        hi.z = pk2(bhi(v[4]), bhi(v[6]));  lo.z = pk2(blo(v[4]), blo(v[6]));
        hi.w = pk2(bhi(v[5]), bhi(v[7]));  lo.w = pk2(blo(v[5]), blo(v[7]));
        const int fs = c * 8 + t;
        g_KA[(fs * 2 + 0) * 32 + lane] = hi;
        g_KA[(fs * 2 + 1) * 32 + lane] = lo;
    }
}

// ---------------------------------------------------------------- main (512 thr)
__global__ void __launch_bounds__(512) k_main(
    const float* __restrict__ embed, const float* __restrict__ bf,
    const float* __restrict__ Wp,    const float* __restrict__ bp)
{
    extern __shared__ __align__(16) unsigned char sm[];
    const int tid = threadIdx.x, wid = tid >> 5, lane = tid & 31;
    const int q = lane >> 2, r = lane & 3;
    const int base = blockIdx.x * TI;
    const uint32_t fb = s2u(sm) + SM_FEAT;
    float* L    = (float*)(sm + SM_L);
    float* part = (float*)(sm + SM_PART);

    // ---- stage embed -> feat rows (hi/lo bf16) ----
    for (int id = tid; id < 4096; id += 512) {
        int row = id >> 5, kq = id & 31;
        int rr = base + row; if (rr >= NQ) rr = NQ - 1;
        float4 v = __ldg((const float4*)&embed[rr * 128 + kq * 4]);
        uint2 h = make_uint2(pk2(bhi(v.x), bhi(v.y)), pk2(bhi(v.z), bhi(v.w)));
        uint2 l = make_uint2(pk2(blo(v.x), blo(v.y)), pk2(blo(v.z), blo(v.w)));
        *(uint2*)(sm + SM_FEAT + row * ROWB + kq * 8)       = h;
        *(uint2*)(sm + SM_FEAT + row * ROWB + 384 + kq * 8) = l;
    }
    if (tid < 128) {    // zero k = 128..191
        uint4 z = make_uint4(0, 0, 0, 0);
#pragma unroll
        for (int j = 0; j < 8; j++) {
            *(uint4*)(sm + SM_FEAT + tid * ROWB + 256 + j * 16) = z;
            *(uint4*)(sm + SM_FEAT + tid * ROWB + 640 + j * 16) = z;
        }
    }
    __syncthreads();

    // ---- GEMM1: logits[m 64][i 128], 16 warps = 4 m-chunks x 4 i-quarters ----
    {
        const int c = wid & 3, quarter = wid >> 2, ib = quarter * 32;
        float cf[4][4];
#pragma unroll
        for (int n = 0; n < 4; n++)
#pragma unroll
            for (int j = 0; j < 4; j++) cf[n][j] = 0.f;
#pragma unroll 1
        for (int t = 0; t < 8; t++) {
            uint4 fah = __ldg(&g_KA[((c * 8 + t) * 2 + 0) * 32 + lane]);
            uint4 fal = __ldg(&g_KA[((c * 8 + t) * 2 + 1) * 32 + lane]);
            uint32_t ah[4] = {fah.x, fah.y, fah.z, fah.w};
            uint32_t al[4] = {fal.x, fal.y, fal.z, fal.w};
#pragma unroll
            for (int n2 = 0; n2 < 2; n2++) {
                uint32_t bh[4], bl[4];
                ldm4(baddr(fb, lane, ib + n2 * 16, t * 32), bh);
                ldm4(baddr(fb, lane, ib + n2 * 16, 384 + t * 32), bl);
                mma16816(cf[n2 * 2],     ah, bh[0], bh[1]);
                mma16816(cf[n2 * 2],     al, bh[0], bh[1]);
                mma16816(cf[n2 * 2],     ah, bl[0], bl[1]);
                mma16816(cf[n2 * 2 + 1], ah, bh[2], bh[3]);
                mma16816(cf[n2 * 2 + 1], al, bh[2], bh[3]);
                mma16816(cf[n2 * 2 + 1], ah, bl[2], bl[3]);
            }
        }
        const int m0 = c * 16 + q;
#pragma unroll
        for (int n = 0; n < 4; n++) {
            int i = ib + n * 8 + 2 * r;
            L[i * 65 + m0]           = cf[n][0];
            L[(i + 1) * 65 + m0]     = cf[n][1];
            L[i * 65 + m0 + 8]       = cf[n][2];
            L[(i + 1) * 65 + m0 + 8] = cf[n][3];
        }
    }
    __syncthreads();

    // ---- softmax per i (thread = one i), write probs into feat k=128..177 ----
    if (tid < 128) {
        const float* row = &L[tid * 65];
        float lg[50], mx = -1e30f;
#pragma unroll
        for (int m = 0; m < 50; m++) { lg[m] = row[m]; mx = fmaxf(mx, lg[m]); }
        float s = 0.f;
#pragma unroll
        for (int m = 0; m < 50; m++) { lg[m] = __expf(lg[m] - mx); s += lg[m]; }
        float inv = 1.f / s;
#pragma unroll
        for (int j = 0; j < 25; j++) {
            float p0 = lg[2 * j] * inv, p1 = lg[2 * j + 1] * inv;
            *(uint32_t*)(sm + SM_FEAT + tid * ROWB + 256 + 4 * j) = pk2(bhi(p0), bhi(p1));
            *(uint32_t*)(sm + SM_FEAT + tid * ROWB + 640 + 4 * j) = pk2(blo(p0), blo(p1));
        }
    }
    __syncthreads();

    // ---- GEMM2: warp = (chunk-pair) x (i-half); 2 outer iters; A-pair per B-sweep ----
    {
        const int ihalf = wid & 1, cpb = wid >> 1;   // cpb 0..7
        float pacc[16];
#pragma unroll
        for (int j = 0; j < 16; j++) pacc[j] = 0.f;
#pragma unroll 1
        for (int iter = 0; iter < 2; iter++) {
            const int cp = cpb + iter * 8;           // chunk-pair 0..15 -> chunks 2cp,2cp+1
            float cf[2][8][4];
#pragma unroll
            for (int u = 0; u < 2; u++)
#pragma unroll
                for (int n = 0; n < 8; n++)
#pragma unroll
                    for (int j = 0; j < 4; j++) cf[u][n][j] = 0.f;
#pragma unroll 1
            for (int t = 0; t < 12; t++) {
                const int fs0 = (2 * cp) * 12 + t;
                const int fs1 = (2 * cp + 1) * 12 + t;
                uint4 f0h = __ldg(&g_WA[(fs0 * 2 + 0) * 32 + lane]);
                uint4 f0l = __ldg(&g_WA[(fs0 * 2 + 1) * 32 + lane]);
                uint4 f1h = __ldg(&g_WA[(fs1 * 2 + 0) * 32 + lane]);
                uint4 f1l = __ldg(&g_WA[(fs1 * 2 + 1) * 32 + lane]);
                uint32_t a0h[4] = {f0h.x, f0h.y, f0h.z, f0h.w};
                uint32_t a0l[4] = {f0l.x, f0l.y, f0l.z, f0l.w};
                uint32_t a1h[4] = {f1h.x, f1h.y, f1h.z, f1h.w};
                uint32_t a1l[4] = {f1l.x, f1l.y, f1l.z, f1l.w};
#pragma unroll
                for (int n2 = 0; n2 < 4; n2++) {
                    const int i0 = ihalf * 64 + n2 * 16;
                    uint32_t bh[4], bl[4];
                    ldm4(baddr(fb, lane, i0, t * 32), bh);
                    ldm4(baddr(fb, lane, i0, 384 + t * 32), bl);
                    mma16816(cf[0][n2 * 2],     a0h, bh[0], bh[1]);
                    mma16816(cf[0][n2 * 2],     a0l, bh[0], bh[1]);
                    mma16816(cf[0][n2 * 2],     a0h, bl[0], bl[1]);
                    mma16816(cf[0][n2 * 2 + 1], a0h, bh[2], bh[3]);
                    mma16816(cf[0][n2 * 2 + 1], a0l, bh[2], bh[3]);
                    mma16816(cf[0][n2 * 2 + 1], a0h, bl[2], bl[3]);
                    mma16816(cf[1][n2 * 2],     a1h, bh[0], bh[1]);
                    mma16816(cf[1][n2 * 2],     a1l, bh[0], bh[1]);
                    mma16816(cf[1][n2 * 2],     a1h, bl[0], bl[1]);
                    mma16816(cf[1][n2 * 2 + 1], a1h, bh[2], bh[3]);
                    mma16816(cf[1][n2 * 2 + 1], a1l, bh[2], bh[3]);
                    mma16816(cf[1][n2 * 2 + 1], a1h, bl[2], bl[3]);
                }
            }
            // epilogue: relu/wp into persistent pacc
#pragma unroll
            for (int u = 0; u < 2; u++) {
                const int ch = 2 * cp + u;
                const int h0 = ch * 16 + q, h1 = h0 + 8;
                float b0 = __ldg(&bf[h0]), b1 = __ldg(&bf[h1]);
                float w0 = __ldg(&Wp[h0]), w1 = __ldg(&Wp[h1]);
#pragma unroll
                for (int n = 0; n < 8; n++) {
                    pacc[2 * n]     += fmaxf(cf[u][n][0] + b0, 0.f) * w0
                                     + fmaxf(cf[u][n][2] + b1, 0.f) * w1;
                    pacc[2 * n + 1] += fmaxf(cf[u][n][1] + b0, 0.f) * w0
                                     + fmaxf(cf[u][n][3] + b1, 0.f) * w1;
                }
            }
        }
        // reduce over the 8 lanes sharing lane%4 (q dimension)
#pragma unroll
        for (int j = 0; j < 16; j++) {
            pacc[j] += __shfl_xor_sync(0xffffffffu, pacc[j], 4);
            pacc[j] += __shfl_xor_sync(0xffffffffu, pacc[j], 8);
            pacc[j] += __shfl_xor_sync(0xffffffffu, pacc[j], 16);
        }
        if (lane < 4) {
#pragma unroll
            for (int n = 0; n < 8; n++) {
                int i = n * 8 + 2 * lane;
                part[wid * 64 + i]     = pacc[2 * n];
                part[wid * 64 + i + 1] = pacc[2 * n + 1];
            }
        }
    }
    __syncthreads();

    // ---- final reduce + sigmoid ----
    if (tid < 128) {
        const int ih = tid >> 6, il = tid & 63;
        float sum = __ldg(bp);
#pragma unroll
        for (int j = 0; j < 8; j++) sum += part[(2 * j + ih) * 64 + il];
        int rr = base + tid;
        if (rr < NQ) g_pred[rr] = 1.f / (1.f + __expf(-sum));
    }
}

// ---------------------------------------------------------------- gather
__global__ void k_gather(const int* __restrict__ q, float* __restrict__ out, int n) {
    int j = (blockIdx.x * blockDim.x + threadIdx.x) * 4;
    if (j + 3 < n) {
        int4 qv = *(const int4*)(q + j);
        float4 o;
        o.x = g_pred[(unsigned)qv.x < NQ ? qv.x : NQ - 1];
        o.y = g_pred[(unsigned)qv.y < NQ ? qv.y : NQ - 1];
        o.z = g_pred[(unsigned)qv.z < NQ ? qv.z : NQ - 1];
        o.w = g_pred[(unsigned)qv.w < NQ ? qv.w : NQ - 1];
        *(float4*)(out + j) = o;
    } else {
        for (; j < n; j++) {
            int idx = q[j];
            out[j] = g_pred[(unsigned)idx < NQ ? idx : NQ - 1];
        }
    }
}

// ---------------------------------------------------------------- launcher
extern "C" void kernel_launch(void* const* d_in, const int* in_sizes, int n_in,
                              void* d_out, int out_size) {
    const int*   q     = (const int*)  d_in[0];
    const float* Kmem  = (const float*)d_in[2];
    const float* V     = (const float*)d_in[3];
    const float* embed = (const float*)d_in[4];
    const float* Wf    = (const float*)d_in[9];
    const float* bf    = (const float*)d_in[10];
    const float* Wp    = (const float*)d_in[11];
    const float* bp    = (const float*)d_in[12];

    k_prep1<<<512, 128>>>(Wf, V);
    k_prep2<<<416, 32>>>(Wf, Kmem);

    cudaFuncSetAttribute(k_main, cudaFuncAttributeMaxDynamicSharedMemorySize, SM_TOTAL);
    k_main<<<NBLK, 512, SM_TOTAL>>>(embed, bf, Wp, bp);

    k_gather<<<(out_size + 1023) / 1024, 256>>>(q, (float*)d_out, out_size);
}

// round 8
// speedup vs baseline: 1.3664x; 1.2928x over previous
#include <cuda_runtime.h>
#include <cuda_fp16.h>
#include <cstdint>

#define NQ 50001
#define TI 128
#define NBLK 391

// feat smem row: [fp16 k0..191 | pad16] = 400 B
#define ROWB 400
#define SM_FEAT 0
#define SM_L    (SM_FEAT + 128 * ROWB)        // logits [128 i][65 f] = 33280
#define SM_PART (SM_L + 128 * 65 * 4)         // partials [8][128] f
#define SM_TOTAL (SM_PART + 8 * 128 * 4)      // 88,576 B -> 2 CTAs/SM

__device__ float g_M1f[512 * 50];
__device__ uint4 g_WA[384 * 2 * 32];          // [chunk*12+t][term hi/lo][lane] A-frags (W, fp16)
__device__ uint4 g_KA[32 * 2 * 32];           // [c*8+t][term][lane] A-frags (Kmem, fp16)
__device__ float g_pred[NQ];

__device__ __forceinline__ uint16_t hhi(float x) {
    return __half_as_ushort(__float2half(x));
}
__device__ __forceinline__ uint16_t hlo(float x) {
    float h = __half2float(__float2half(x));
    return __half_as_ushort(__float2half(x - h));
}
__device__ __forceinline__ uint32_t pk2(uint16_t a, uint16_t b) {
    return (uint32_t)a | ((uint32_t)b << 16);
}
__device__ __forceinline__ uint32_t s2u(const void* p) {
    uint32_t a;
    asm("{ .reg .u64 t; cvta.to.shared.u64 t, %1; cvt.u32.u64 %0, t; }" : "=r"(a) : "l"(p));
    return a;
}
__device__ __forceinline__ void ldm4(uint32_t addr, uint32_t* r) {
    asm volatile("ldmatrix.sync.aligned.m8n8.x4.shared.b16 {%0,%1,%2,%3}, [%4];"
                 : "=r"(r[0]), "=r"(r[1]), "=r"(r[2]), "=r"(r[3]) : "r"(addr));
}
__device__ __forceinline__ void mma16816(float* c, const uint32_t* a, uint32_t b0, uint32_t b1) {
    asm volatile("mma.sync.aligned.m16n8k16.row.col.f32.f16.f16.f32 "
                 "{%0,%1,%2,%3}, {%4,%5,%6,%7}, {%8,%9}, {%0,%1,%2,%3};"
                 : "+f"(c[0]), "+f"(c[1]), "+f"(c[2]), "+f"(c[3])
                 : "r"(a[0]), "r"(a[1]), "r"(a[2]), "r"(a[3]), "r"(b0), "r"(b1));
}
// per-lane ldmatrix address for B tile-pair (i0..i0+15) x (k-step bytes kb0..+31)
__device__ __forceinline__ uint32_t baddr(uint32_t fb, int lane, int i0, int kb0) {
    int row = i0 + (lane & 7) + ((lane & 16) ? 8 : 0);
    int col = (lane & 8) ? 16 : 0;
    return fb + row * ROWB + kb0 + col;
}

// ---------------------------------------------------------------- prep1: M1
__global__ void k_prep1(const float* __restrict__ Wf, const float* __restrict__ V) {
    __shared__ float wrow[256];
    __shared__ float p2[100];
    const int b = blockIdx.x, t = threadIdx.x;   // 512 x 128
    for (int e = t; e < 256; e += 128) wrow[e] = Wf[b * 384 + e];
    __syncthreads();
    if (t < 100) {
        int m = t >> 1, half = (t & 1) * 128;
        const float* vp = V + m * 256 + half;
        const float* wp2 = wrow + half;
        float s = 0.f;
#pragma unroll 16
        for (int v = 0; v < 128; v++) s += wp2[v] * __ldg(vp + v);
        p2[t] = s;
    }
    __syncthreads();
    if (t < 50) g_M1f[b * 50 + t] = p2[2 * t] + p2[2 * t + 1];
}

// ---------------------------------------------------------------- prep2: frag pack (fp16)
__global__ void k_prep2(const float* __restrict__ Wf, const float* __restrict__ Km) {
    const int b = blockIdx.x, lane = threadIdx.x;   // 416 x 32
    const int q = lane >> 2, r = lane & 3;
    if (b < 384) {
        const int s = b / 48, rem = b % 48, c = rem / 12, t = rem % 12;
        const int h0 = s * 64 + c * 16 + q, h1 = h0 + 8;
        const int k0 = t * 16 + 2 * r;
        float v[8];
#pragma unroll
        for (int j = 0; j < 8; j++) {
            int h = (j & 1) ? h1 : h0;
            int k = k0 + ((j >> 2) ? 8 : 0) + ((j >> 1) & 1);
            v[j] = (k < 128) ? Wf[h * 384 + 256 + k]
                             : ((k < 178) ? g_M1f[h * 50 + (k - 128)] : 0.f);
        }
        uint4 hi, lo;
        hi.x = pk2(hhi(v[0]), hhi(v[2]));  lo.x = pk2(hlo(v[0]), hlo(v[2]));
        hi.y = pk2(hhi(v[1]), hhi(v[3]));  lo.y = pk2(hlo(v[1]), hlo(v[3]));
        hi.z = pk2(hhi(v[4]), hhi(v[6]));  lo.z = pk2(hlo(v[4]), hlo(v[6]));
        hi.w = pk2(hhi(v[5]), hhi(v[7]));  lo.w = pk2(hlo(v[5]), hlo(v[7]));
        const int fs = (s * 4 + c) * 12 + t;
        g_WA[(fs * 2 + 0) * 32 + lane] = hi;
        g_WA[(fs * 2 + 1) * 32 + lane] = lo;
    } else {
        const int kb = b - 384, c = kb / 8, t = kb % 8;
        const int m0 = c * 16 + q, m1 = m0 + 8;
        const int k0 = t * 16 + 2 * r;
        float v[8];
#pragma unroll
        for (int j = 0; j < 8; j++) {
            int m = (j & 1) ? m1 : m0;
            int k = k0 + ((j >> 2) ? 8 : 0) + ((j >> 1) & 1);
            v[j] = (m < 50) ? Km[m * 128 + k] : 0.f;
        }
        uint4 hi, lo;
        hi.x = pk2(hhi(v[0]), hhi(v[2]));  lo.x = pk2(hlo(v[0]), hlo(v[2]));
        hi.y = pk2(hhi(v[1]), hhi(v[3]));  lo.y = pk2(hlo(v[1]), hlo(v[3]));
        hi.z = pk2(hhi(v[4]), hhi(v[6]));  lo.z = pk2(hlo(v[4]), hlo(v[6]));
        hi.w = pk2(hhi(v[5]), hhi(v[7]));  lo.w = pk2(hlo(v[5]), hlo(v[7]));
        const int fs = c * 8 + t;
        g_KA[(fs * 2 + 0) * 32 + lane] = hi;
        g_KA[(fs * 2 + 1) * 32 + lane] = lo;
    }
}

// ---------------------------------------------------------------- main (256 thr, 2 CTA/SM)
__global__ void __launch_bounds__(256, 2) k_main(
    const float* __restrict__ embed, const float* __restrict__ bf,
    const float* __restrict__ Wp,    const float* __restrict__ bp)
{
    extern __shared__ __align__(16) unsigned char sm[];
    const int tid = threadIdx.x, wid = tid >> 5, lane = tid & 31;
    const int q = lane >> 2, r = lane & 3;
    const int base = blockIdx.x * TI;
    const uint32_t fb = s2u(sm) + SM_FEAT;
    float* L    = (float*)(sm + SM_L);
    float* part = (float*)(sm + SM_PART);

    // ---- stage embed -> feat rows (fp16) ----
    for (int id = tid; id < 4096; id += 256) {
        int row = id >> 5, kq = id & 31;
        int rr = base + row; if (rr >= NQ) rr = NQ - 1;
        float4 v = __ldg((const float4*)&embed[rr * 128 + kq * 4]);
        uint2 h = make_uint2(pk2(hhi(v.x), hhi(v.y)), pk2(hhi(v.z), hhi(v.w)));
        *(uint2*)(sm + SM_FEAT + row * ROWB + kq * 8) = h;
    }
    if (tid < 128) {    // zero k = 128..191 (bytes 256..384)
        uint4 z = make_uint4(0, 0, 0, 0);
#pragma unroll
        for (int j = 0; j < 8; j++)
            *(uint4*)(sm + SM_FEAT + tid * ROWB + 256 + j * 16) = z;
    }
    __syncthreads();

    // ---- GEMM1: logits[m 64][i 128] = Kmem . feat^T (2-term A split) ----
    {
        const int c = wid & 3, half = wid >> 2, ib = half * 64;
        float cf[8][4];
#pragma unroll
        for (int n = 0; n < 8; n++)
#pragma unroll
            for (int j = 0; j < 4; j++) cf[n][j] = 0.f;
#pragma unroll 1
        for (int t = 0; t < 8; t++) {
            uint4 fah = __ldg(&g_KA[((c * 8 + t) * 2 + 0) * 32 + lane]);
            uint4 fal = __ldg(&g_KA[((c * 8 + t) * 2 + 1) * 32 + lane]);
            uint32_t ah[4] = {fah.x, fah.y, fah.z, fah.w};
            uint32_t al[4] = {fal.x, fal.y, fal.z, fal.w};
#pragma unroll
            for (int n2 = 0; n2 < 4; n2++) {
                uint32_t bh[4];
                ldm4(baddr(fb, lane, ib + n2 * 16, t * 32), bh);
                mma16816(cf[n2 * 2],     ah, bh[0], bh[1]);
                mma16816(cf[n2 * 2],     al, bh[0], bh[1]);
                mma16816(cf[n2 * 2 + 1], ah, bh[2], bh[3]);
                mma16816(cf[n2 * 2 + 1], al, bh[2], bh[3]);
            }
        }
        const int m0 = c * 16 + q;
#pragma unroll
        for (int n = 0; n < 8; n++) {
            int i = ib + n * 8 + 2 * r;
            L[i * 65 + m0]           = cf[n][0];
            L[(i + 1) * 65 + m0]     = cf[n][1];
            L[i * 65 + m0 + 8]       = cf[n][2];
            L[(i + 1) * 65 + m0 + 8] = cf[n][3];
        }
    }
    __syncthreads();

    // ---- softmax per i (thread = one i), write probs (fp16) into feat k=128..177 ----
    if (tid < 128) {
        const float* row = &L[tid * 65];
        float lg[50], mx = -1e30f;
#pragma unroll
        for (int m = 0; m < 50; m++) { lg[m] = row[m]; mx = fmaxf(mx, lg[m]); }
        float s = 0.f;
#pragma unroll
        for (int m = 0; m < 50; m++) { lg[m] = __expf(lg[m] - mx); s += lg[m]; }
        float inv = 1.f / s;
#pragma unroll
        for (int j = 0; j < 25; j++) {
            float p0 = lg[2 * j] * inv, p1 = lg[2 * j + 1] * inv;
            *(uint32_t*)(sm + SM_FEAT + tid * ROWB + 256 + 4 * j) = pk2(hhi(p0), hhi(p1));
        }
    }
    __syncthreads();

    // ---- GEMM2: per warp strip s (64 h), 4 chunks; 2-term A split ----
    {
        const int s = wid;
        float pacc[32];
#pragma unroll
        for (int j = 0; j < 32; j++) pacc[j] = 0.f;
#pragma unroll 1
        for (int c = 0; c < 4; c++) {
            float cf[16][4];
#pragma unroll
            for (int n = 0; n < 16; n++)
#pragma unroll
                for (int j = 0; j < 4; j++) cf[n][j] = 0.f;
#pragma unroll 1
            for (int t = 0; t < 12; t++) {
                const int fs = (s * 4 + c) * 12 + t;
                uint4 fah = __ldg(&g_WA[(fs * 2 + 0) * 32 + lane]);
                uint4 fal = __ldg(&g_WA[(fs * 2 + 1) * 32 + lane]);
                uint32_t ah[4] = {fah.x, fah.y, fah.z, fah.w};
                uint32_t al[4] = {fal.x, fal.y, fal.z, fal.w};
#pragma unroll
                for (int n2 = 0; n2 < 8; n2++) {
                    uint32_t bh[4];
                    ldm4(baddr(fb, lane, n2 * 16, t * 32), bh);
                    mma16816(cf[n2 * 2],     ah, bh[0], bh[1]);
                    mma16816(cf[n2 * 2],     al, bh[0], bh[1]);
                    mma16816(cf[n2 * 2 + 1], ah, bh[2], bh[3]);
                    mma16816(cf[n2 * 2 + 1], al, bh[2], bh[3]);
                }
            }
            const int h0 = s * 64 + c * 16 + q, h1 = h0 + 8;
            float b0 = __ldg(&bf[h0]), b1 = __ldg(&bf[h1]);
            float w0 = __ldg(&Wp[h0]), w1 = __ldg(&Wp[h1]);
#pragma unroll
            for (int n = 0; n < 16; n++) {
                pacc[2 * n]     += fmaxf(cf[n][0] + b0, 0.f) * w0 + fmaxf(cf[n][2] + b1, 0.f) * w1;
                pacc[2 * n + 1] += fmaxf(cf[n][1] + b0, 0.f) * w0 + fmaxf(cf[n][3] + b1, 0.f) * w1;
            }
        }
        // reduce over the 8 lanes sharing lane%4
#pragma unroll
        for (int j = 0; j < 32; j++) {
            pacc[j] += __shfl_xor_sync(0xffffffffu, pacc[j], 4);
            pacc[j] += __shfl_xor_sync(0xffffffffu, pacc[j], 8);
            pacc[j] += __shfl_xor_sync(0xffffffffu, pacc[j], 16);
        }
        if (lane < 4) {
#pragma unroll
            for (int n = 0; n < 16; n++) {
                int i = n * 8 + 2 * lane;
                part[s * 128 + i]     = pacc[2 * n];
                part[s * 128 + i + 1] = pacc[2 * n + 1];
            }
        }
    }
    __syncthreads();

    // ---- final reduce + sigmoid ----
    if (tid < 128) {
        float sum = __ldg(bp);
#pragma unroll
        for (int s = 0; s < 8; s++) sum += part[s * 128 + tid];
        int rr = base + tid;
        if (rr < NQ) g_pred[rr] = 1.f / (1.f + __expf(-sum));
    }
}

// ---------------------------------------------------------------- gather
__global__ void k_gather(const int* __restrict__ q, float* __restrict__ out, int n) {
    int j = (blockIdx.x * blockDim.x + threadIdx.x) * 4;
    if (j + 3 < n) {
        int4 qv = *(const int4*)(q + j);
        float4 o;
        o.x = g_pred[(unsigned)qv.x < NQ ? qv.x : NQ - 1];
        o.y = g_pred[(unsigned)qv.y < NQ ? qv.y : NQ - 1];
        o.z = g_pred[(unsigned)qv.z < NQ ? qv.z : NQ - 1];
        o.w = g_pred[(unsigned)qv.w < NQ ? qv.w : NQ - 1];
        *(float4*)(out + j) = o;
    } else {
        for (; j < n; j++) {
            int idx = q[j];
            out[j] = g_pred[(unsigned)idx < NQ ? idx : NQ - 1];
        }
    }
}

// ---------------------------------------------------------------- launcher
extern "C" void kernel_launch(void* const* d_in, const int* in_sizes, int n_in,
                              void* d_out, int out_size) {
    const int*   q     = (const int*)  d_in[0];
    const float* Kmem  = (const float*)d_in[2];
    const float* V     = (const float*)d_in[3];
    const float* embed = (const float*)d_in[4];
    const float* Wf    = (const float*)d_in[9];
    const float* bf    = (const float*)d_in[10];
    const float* Wp    = (const float*)d_in[11];
    const float* bp    = (const float*)d_in[12];

    k_prep1<<<512, 128>>>(Wf, V);
    k_prep2<<<416, 32>>>(Wf, Kmem);

    cudaFuncSetAttribute(k_main, cudaFuncAttributeMaxDynamicSharedMemorySize, SM_TOTAL);
    k_main<<<NBLK, 256, SM_TOTAL>>>(embed, bf, Wp, bp);

    k_gather<<<(out_size + 1023) / 1024, 256>>>(q, (float*)d_out, out_size);
}

// round 9
// speedup vs baseline: 1.5126x; 1.1070x over previous
#include <cuda_runtime.h>
#include <cuda_fp16.h>
#include <cstdint>

#define NQ 50001
#define TI 128
#define NBLK 391

// feat smem row: [fp16 k0..191 | pad16] = 400 B
#define ROWB 400
#define SM_FEAT 0
#define SM_L    (SM_FEAT + 128 * ROWB)        // logits [128 i][65 f]
#define SM_PART (SM_L + 128 * 65 * 4)         // partials [8][128] f
#define SM_TOTAL (SM_PART + 8 * 128 * 4)      // 88,576 B -> 2 CTAs/SM

__device__ float g_M1f[512 * 50];
__device__ uint4 g_WA[384 * 32];              // [chunk*12+t][lane] A-frags (W, fp16)
__device__ uint4 g_KA[32 * 32];               // [c*8+t][lane] A-frags (Kmem, fp16)
__device__ float g_pred[NQ];

__device__ __forceinline__ uint16_t hhi(float x) {
    return __half_as_ushort(__float2half(x));
}
__device__ __forceinline__ uint32_t pk2(uint16_t a, uint16_t b) {
    return (uint32_t)a | ((uint32_t)b << 16);
}
__device__ __forceinline__ uint32_t s2u(const void* p) {
    uint32_t a;
    asm("{ .reg .u64 t; cvta.to.shared.u64 t, %1; cvt.u32.u64 %0, t; }" : "=r"(a) : "l"(p));
    return a;
}
__device__ __forceinline__ void ldm4(uint32_t addr, uint32_t* r) {
    asm volatile("ldmatrix.sync.aligned.m8n8.x4.shared.b16 {%0,%1,%2,%3}, [%4];"
                 : "=r"(r[0]), "=r"(r[1]), "=r"(r[2]), "=r"(r[3]) : "r"(addr));
}
__device__ __forceinline__ void mma16816(float* c, const uint32_t* a, uint32_t b0, uint32_t b1) {
    asm volatile("mma.sync.aligned.m16n8k16.row.col.f32.f16.f16.f32 "
                 "{%0,%1,%2,%3}, {%4,%5,%6,%7}, {%8,%9}, {%0,%1,%2,%3};"
                 : "+f"(c[0]), "+f"(c[1]), "+f"(c[2]), "+f"(c[3])
                 : "r"(a[0]), "r"(a[1]), "r"(a[2]), "r"(a[3]), "r"(b0), "r"(b1));
}
// per-lane ldmatrix address for B tile-pair (i0..i0+15) x (k-step bytes kb0..+31)
__device__ __forceinline__ uint32_t baddr(uint32_t fb, int lane, int i0, int kb0) {
    int row = i0 + (lane & 7) + ((lane & 16) ? 8 : 0);
    int col = (lane & 8) ? 16 : 0;
    return fb + row * ROWB + kb0 + col;
}

// ---------------------------------------------------------------- prep1: M1
__global__ void k_prep1(const float* __restrict__ Wf, const float* __restrict__ V) {
    __shared__ float wrow[256];
    __shared__ float p2[100];
    const int b = blockIdx.x, t = threadIdx.x;   // 512 x 128
    for (int e = t; e < 256; e += 128) wrow[e] = Wf[b * 384 + e];
    __syncthreads();
    if (t < 100) {
        int m = t >> 1, half = (t & 1) * 128;
        const float* vp = V + m * 256 + half;
        const float* wp2 = wrow + half;
        float s = 0.f;
#pragma unroll 16
        for (int v = 0; v < 128; v++) s += wp2[v] * __ldg(vp + v);
        p2[t] = s;
    }
    __syncthreads();
    if (t < 50) g_M1f[b * 50 + t] = p2[2 * t] + p2[2 * t + 1];
}

// ---------------------------------------------------------------- prep2: frag pack (fp16, 1 term)
__global__ void k_prep2(const float* __restrict__ Wf, const float* __restrict__ Km) {
    const int b = blockIdx.x, lane = threadIdx.x;   // 416 x 32
    const int q = lane >> 2, r = lane & 3;
    if (b < 384) {
        const int s = b / 48, rem = b % 48, c = rem / 12, t = rem % 12;
        const int h0 = s * 64 + c * 16 + q, h1 = h0 + 8;
        const int k0 = t * 16 + 2 * r;
        float v[8];
#pragma unroll
        for (int j = 0; j < 8; j++) {
            int h = (j & 1) ? h1 : h0;
            int k = k0 + ((j >> 2) ? 8 : 0) + ((j >> 1) & 1);
            v[j] = (k < 128) ? Wf[h * 384 + 256 + k]
                             : ((k < 178) ? g_M1f[h * 50 + (k - 128)] : 0.f);
        }
        uint4 hi;
        hi.x = pk2(hhi(v[0]), hhi(v[2]));
        hi.y = pk2(hhi(v[1]), hhi(v[3]));
        hi.z = pk2(hhi(v[4]), hhi(v[6]));
        hi.w = pk2(hhi(v[5]), hhi(v[7]));
        const int fs = (s * 4 + c) * 12 + t;
        g_WA[fs * 32 + lane] = hi;
    } else {
        const int kb = b - 384, c = kb / 8, t = kb % 8;
        const int m0 = c * 16 + q, m1 = m0 + 8;
        const int k0 = t * 16 + 2 * r;
        float v[8];
#pragma unroll
        for (int j = 0; j < 8; j++) {
            int m = (j & 1) ? m1 : m0;
            int k = k0 + ((j >> 2) ? 8 : 0) + ((j >> 1) & 1);
            v[j] = (m < 50) ? Km[m * 128 + k] : 0.f;
        }
        uint4 hi;
        hi.x = pk2(hhi(v[0]), hhi(v[2]));
        hi.y = pk2(hhi(v[1]), hhi(v[3]));
        hi.z = pk2(hhi(v[4]), hhi(v[6]));
        hi.w = pk2(hhi(v[5]), hhi(v[7]));
        const int fs = c * 8 + t;
        g_KA[fs * 32 + lane] = hi;
    }
}

// ---------------------------------------------------------------- main (256 thr, 2 CTA/SM)
__global__ void __launch_bounds__(256, 2) k_main(
    const float* __restrict__ embed, const float* __restrict__ bf,
    const float* __restrict__ Wp,    const float* __restrict__ bp)
{
    extern __shared__ __align__(16) unsigned char sm[];
    const int tid = threadIdx.x, wid = tid >> 5, lane = tid & 31;
    const int q = lane >> 2, r = lane & 3;
    const int base = blockIdx.x * TI;
    const uint32_t fb = s2u(sm) + SM_FEAT;
    float* L    = (float*)(sm + SM_L);
    float* part = (float*)(sm + SM_PART);

    // ---- stage embed -> feat rows (fp16) ----
    for (int id = tid; id < 4096; id += 256) {
        int row = id >> 5, kq = id & 31;
        int rr = base + row; if (rr >= NQ) rr = NQ - 1;
        float4 v = __ldg((const float4*)&embed[rr * 128 + kq * 4]);
        uint2 h = make_uint2(pk2(hhi(v.x), hhi(v.y)), pk2(hhi(v.z), hhi(v.w)));
        *(uint2*)(sm + SM_FEAT + row * ROWB + kq * 8) = h;
    }
    if (tid < 128) {    // zero k = 128..191 (bytes 256..384)
        uint4 z = make_uint4(0, 0, 0, 0);
#pragma unroll
        for (int j = 0; j < 8; j++)
            *(uint4*)(sm + SM_FEAT + tid * ROWB + 256 + j * 16) = z;
    }
    __syncthreads();

    // ---- GEMM1: logits[m 64][i 128] = Kmem . feat^T ----
    {
        const int c = wid & 3, half = wid >> 2, ib = half * 64;
        float cf[8][4];
#pragma unroll
        for (int n = 0; n < 8; n++)
#pragma unroll
            for (int j = 0; j < 4; j++) cf[n][j] = 0.f;
#pragma unroll 1
        for (int t = 0; t < 8; t++) {
            uint4 fah = __ldg(&g_KA[(c * 8 + t) * 32 + lane]);
            uint32_t ah[4] = {fah.x, fah.y, fah.z, fah.w};
#pragma unroll
            for (int n2 = 0; n2 < 4; n2++) {
                uint32_t bh[4];
                ldm4(baddr(fb, lane, ib + n2 * 16, t * 32), bh);
                mma16816(cf[n2 * 2],     ah, bh[0], bh[1]);
                mma16816(cf[n2 * 2 + 1], ah, bh[2], bh[3]);
            }
        }
        const int m0 = c * 16 + q;
#pragma unroll
        for (int n = 0; n < 8; n++) {
            int i = ib + n * 8 + 2 * r;
            L[i * 65 + m0]           = cf[n][0];
            L[(i + 1) * 65 + m0]     = cf[n][1];
            L[i * 65 + m0 + 8]       = cf[n][2];
            L[(i + 1) * 65 + m0 + 8] = cf[n][3];
        }
    }
    __syncthreads();

    // ---- softmax per i (thread = one i), write probs (fp16) into feat k=128..177 ----
    if (tid < 128) {
        const float* row = &L[tid * 65];
        float lg[50], mx = -1e30f;
#pragma unroll
        for (int m = 0; m < 50; m++) { lg[m] = row[m]; mx = fmaxf(mx, lg[m]); }
        float s = 0.f;
#pragma unroll
        for (int m = 0; m < 50; m++) { lg[m] = __expf(lg[m] - mx); s += lg[m]; }
        float inv = 1.f / s;
#pragma unroll
        for (int j = 0; j < 25; j++) {
            float p0 = lg[2 * j] * inv, p1 = lg[2 * j + 1] * inv;
            *(uint32_t*)(sm + SM_FEAT + tid * ROWB + 256 + 4 * j) = pk2(hhi(p0), hhi(p1));
        }
    }
    __syncthreads();

    // ---- GEMM2: per warp strip s (64 h), 4 chunks ----
    {
        const int s = wid;
        float pacc[32];
#pragma unroll
        for (int j = 0; j < 32; j++) pacc[j] = 0.f;
#pragma unroll 1
        for (int c = 0; c < 4; c++) {
            float cf[16][4];
#pragma unroll
            for (int n = 0; n < 16; n++)
#pragma unroll
                for (int j = 0; j < 4; j++) cf[n][j] = 0.f;
#pragma unroll 1
            for (int t = 0; t < 12; t++) {
                const int fs = (s * 4 + c) * 12 + t;
                uint4 fah = __ldg(&g_WA[fs * 32 + lane]);
                uint32_t ah[4] = {fah.x, fah.y, fah.z, fah.w};
#pragma unroll
                for (int n2 = 0; n2 < 8; n2++) {
                    uint32_t bh[4];
                    ldm4(baddr(fb, lane, n2 * 16, t * 32), bh);
                    mma16816(cf[n2 * 2],     ah, bh[0], bh[1]);
                    mma16816(cf[n2 * 2 + 1], ah, bh[2], bh[3]);
                }
            }
            const int h0 = s * 64 + c * 16 + q, h1 = h0 + 8;
            float b0 = __ldg(&bf[h0]), b1 = __ldg(&bf[h1]);
            float w0 = __ldg(&Wp[h0]), w1 = __ldg(&Wp[h1]);
#pragma unroll
            for (int n = 0; n < 16; n++) {
                pacc[2 * n]     += fmaxf(cf[n][0] + b0, 0.f) * w0 + fmaxf(cf[n][2] + b1, 0.f) * w1;
                pacc[2 * n + 1] += fmaxf(cf[n][1] + b0, 0.f) * w0 + fmaxf(cf[n][3] + b1, 0.f) * w1;
            }
        }
        // reduce over the 8 lanes sharing lane%4
#pragma unroll
        for (int j = 0; j < 32; j++) {
            pacc[j] += __shfl_xor_sync(0xffffffffu, pacc[j], 4);
            pacc[j] += __shfl_xor_sync(0xffffffffu, pacc[j], 8);
            pacc[j] += __shfl_xor_sync(0xffffffffu, pacc[j], 16);
        }
        if (lane < 4) {
#pragma unroll
            for (int n = 0; n < 16; n++) {
                int i = n * 8 + 2 * lane;
                part[s * 128 + i]     = pacc[2 * n];
                part[s * 128 + i + 1] = pacc[2 * n + 1];
            }
        }
    }
    __syncthreads();

    // ---- final reduce + sigmoid ----
    if (tid < 128) {
        float sum = __ldg(bp);
#pragma unroll
        for (int s = 0; s < 8; s++) sum += part[s * 128 + tid];
        int rr = base + tid;
        if (rr < NQ) g_pred[rr] = 1.f / (1.f + __expf(-sum));
    }
}

// ---------------------------------------------------------------- gather
__global__ void k_gather(const int* __restrict__ q, float* __restrict__ out, int n) {
    int j = (blockIdx.x * blockDim.x + threadIdx.x) * 4;
    if (j + 3 < n) {
        int4 qv = *(const int4*)(q + j);
        float4 o;
        o.x = g_pred[(unsigned)qv.x < NQ ? qv.x : NQ - 1];
        o.y = g_pred[(unsigned)qv.y < NQ ? qv.y : NQ - 1];
        o.z = g_pred[(unsigned)qv.z < NQ ? qv.z : NQ - 1];
        o.w = g_pred[(unsigned)qv.w < NQ ? qv.w : NQ - 1];
        *(float4*)(out + j) = o;
    } else {
        for (; j < n; j++) {
            int idx = q[j];
            out[j] = g_pred[(unsigned)idx < NQ ? idx : NQ - 1];
        }
    }
}

// ---------------------------------------------------------------- launcher
extern "C" void kernel_launch(void* const* d_in, const int* in_sizes, int n_in,
                              void* d_out, int out_size) {
    const int*   q     = (const int*)  d_in[0];
    const float* Kmem  = (const float*)d_in[2];
    const float* V     = (const float*)d_in[3];
    const float* embed = (const float*)d_in[4];
    const float* Wf    = (const float*)d_in[9];
    const float* bf    = (const float*)d_in[10];
    const float* Wp    = (const float*)d_in[11];
    const float* bp    = (const float*)d_in[12];

    k_prep1<<<512, 128>>>(Wf, V);
    k_prep2<<<416, 32>>>(Wf, Kmem);

    cudaFuncSetAttribute(k_main, cudaFuncAttributeMaxDynamicSharedMemorySize, SM_TOTAL);
    k_main<<<NBLK, 256, SM_TOTAL>>>(embed, bf, Wp, bp);

    k_gather<<<(out_size + 1023) / 1024, 256>>>(q, (float*)d_out, out_size);
}